// round 15
// baseline (speedup 1.0000x reference)
#include <cuda_runtime.h>
#include <cuda_fp16.h>
#include <cstdint>

#define NPTS  2048
#define BATCH 8
#define CINCH 64
#define COUTC 128
#define KNNK  16
#define NTILES 2048   // 8 points per tile

// d_out partitioning (float elements)
constexpr size_t OUT2_OFF = (size_t)BATCH * COUTC * NPTS;                     // 2,097,152
constexpr size_t LC_OFF   = OUT2_OFF + (size_t)BATCH * COUTC * NPTS * KNNK;   // 35,651,584

__device__ int   g_idx[BATCH * NPTS * KNNK];
__device__ float g_xt[BATCH * NPTS * CINCH];   // x transposed to [b][n][c]

__device__ __forceinline__ unsigned long long umin64(unsigned long long a,
                                                     unsigned long long b) {
    return a < b ? a : b;
}

__device__ __forceinline__ uint32_t packh2(__half a, __half b) {
    return (uint32_t)__half_as_ushort(a) | ((uint32_t)__half_as_ushort(b) << 16);
}
// fp16 hi/lo split of two floats -> packed hi pair, lo pair
__device__ __forceinline__ void h2split(float a, float b, uint32_t& hi, uint32_t& lo) {
    __half ah = __float2half_rn(a), bh = __float2half_rn(b);
    __half al = __float2half_rn(a - __half2float(ah));
    __half bl = __float2half_rn(b - __half2float(bh));
    hi = packh2(ah, bh);
    lo = packh2(al, bl);
}
__device__ __forceinline__ void hsplit(float a, __half& h, __half& l) {
    h = __float2half_rn(a);
    l = __float2half_rn(a - __half2float(h));
}

#define MMA_F16(c, a0, a1, a2, a3, b0, b1)                                       \
    asm volatile(                                                                \
        "mma.sync.aligned.m16n8k16.row.col.f32.f16.f16.f32 "                     \
        "{%0,%1,%2,%3}, {%4,%5,%6,%7}, {%8,%9}, {%0,%1,%2,%3};"                  \
        : "+f"((c)[0]), "+f"((c)[1]), "+f"((c)[2]), "+f"((c)[3])                 \
        : "r"(a0), "r"(a1), "r"(a2), "r"(a3), "r"(b0), "r"(b1))

// ---------- kernel 0: transpose x[b][c][n] -> g_xt[b][n][c] ----------
__global__ void __launch_bounds__(256) transpose_kernel(const float* __restrict__ x) {
    __shared__ float t[64][65];
    const int b = blockIdx.y, n0 = blockIdx.x * 64;
    const int tid = threadIdx.x;
    const int nn = tid & 63, cq = tid >> 6;
#pragma unroll
    for (int i = 0; i < 16; ++i) {
        int c = i * 4 + cq;
        t[c][nn] = x[((size_t)b * CINCH + c) * NPTS + n0 + nn];
    }
    __syncthreads();
    const int nr = tid >> 2, q = tid & 3;
    float4* dst = (float4*)(g_xt + ((size_t)b * NPTS + n0 + nr) * CINCH);
#pragma unroll
    for (int i = 0; i < 4; ++i) {
        int c4 = i * 4 + q;
        dst[c4] = make_float4(t[c4 * 4 + 0][nr], t[c4 * 4 + 1][nr],
                              t[c4 * 4 + 2][nr], t[c4 * 4 + 3][nr]);
    }
}

// ---------- kernel 1: KNN (top-16 ascending d2, tie -> smaller index) + local coords ----
// Round = shfl allreduce -> ONE bar (double-buffered wmin) -> all threads merge 8 warp
// minima locally -> owner invalidates + recomputes. Winner keys latched in registers.
__global__ void __launch_bounds__(256, 5) knn_kernel(const float* __restrict__ coords,
                                                     float* __restrict__ dout) {
    const int bn = blockIdx.x;
    const int b = bn >> 11, n = bn & (NPTS - 1);
    const int tid = threadIdx.x;
    const int w = tid >> 5, lane = tid & 31;
    const float* cb = coords + (size_t)b * 3 * NPTS;
    const float qx = cb[n], qy = cb[NPTS + n], qz = cb[2 * NPTS + n];
    const float sqn = __fadd_rn(__fadd_rn(__fmul_rn(qx, qx), __fmul_rn(qy, qy)),
                                __fmul_rn(qz, qz));

    unsigned long long keys[8];
#pragma unroll
    for (int i = 0; i < 8; ++i) {
        int m = tid + (i << 8);
        float mx = cb[m], my = cb[NPTS + m], mz = cb[2 * NPTS + m];
        float sqm = __fadd_rn(__fadd_rn(__fmul_rn(mx, mx), __fmul_rn(my, my)),
                              __fmul_rn(mz, mz));
        float dot = fmaf(qz, mz, fmaf(qy, my, __fmul_rn(qx, mx)));
        float t  = __fadd_rn(sqn, sqm);
        float d2 = __fsub_rn(t, __fmul_rn(2.0f, dot));
        unsigned u = __float_as_uint(d2);
        u = (u & 0x80000000u) ? ~u : (u | 0x80000000u);
        keys[i] = ((unsigned long long)u << 32) | (unsigned)m;
    }

    unsigned long long tmin =
        umin64(umin64(umin64(keys[0], keys[1]), umin64(keys[2], keys[3])),
               umin64(umin64(keys[4], keys[5]), umin64(keys[6], keys[7])));

    __shared__ unsigned long long wmin[2][8];
    unsigned long long mykey = 0;
    const int myr = tid & 15;

#pragma unroll 1
    for (int r = 0; r < KNNK; ++r) {
        unsigned long long v = tmin;
#pragma unroll
        for (int off = 16; off; off >>= 1)
            v = umin64(v, __shfl_xor_sync(0xffffffffu, v, off));
        if (lane == 0) wmin[r & 1][w] = v;
        __syncthreads();
        const unsigned long long* wm = wmin[r & 1];
        unsigned long long bb =
            umin64(umin64(umin64(wm[0], wm[1]), umin64(wm[2], wm[3])),
                   umin64(umin64(wm[4], wm[5]), umin64(wm[6], wm[7])));
        if (myr == r) mykey = bb;
        if (tmin == bb) {                     // exactly one owner thread per block
#pragma unroll
            for (int i = 0; i < 8; ++i)
                keys[i] = (keys[i] == bb) ? ~0ull : keys[i];
            tmin = umin64(umin64(umin64(keys[0], keys[1]), umin64(keys[2], keys[3])),
                          umin64(umin64(keys[4], keys[5]), umin64(keys[6], keys[7])));
        }
    }

    if (tid < KNNK) g_idx[bn * KNNK + tid] = (int)(mykey & 0xffffffffull);
    if (tid < 3 * KNNK) {
        int c = tid >> 4, k = tid & 15;  // k == myr
        int id = (int)(mykey & 0xffffffffull);
        float center = cb[c * NPTS + n];
        float nb = cb[c * NPTS + id];
        dout[LC_OFF + (((size_t)(b * 3 + c) * NPTS) + n) * KNNK + k] = __fsub_rn(center, nb);
    }
}

// ---------- kernel 2: persistent mma.sync 3xFP16-split MLP ----------
// 152 CTAs x 512 thr (16 warps). Tile = 8 points = 128 cols.
// Warp w: rows 16*(w&7)..+15, cols 64*(w>>3)..+63.
#define W1S 36
#define W2S 68
#define HSS 68
#define XS  136
__global__ void __launch_bounds__(512, 1) mlp_mma_kernel(
    const float* __restrict__ w1, const float* __restrict__ w2,
    const float* __restrict__ g1, const float* __restrict__ b1,
    const float* __restrict__ m1, const float* __restrict__ v1,
    const float* __restrict__ g2, const float* __restrict__ b2,
    const float* __restrict__ m2, const float* __restrict__ v2,
    float* __restrict__ dout) {
    extern __shared__ uint32_t sm[];
    uint32_t* W1HI = sm;                  // 4608
    uint32_t* W1LO = sm + 4608;           // 4608
    uint32_t* W2HI = sm + 9216;           // 8704
    uint32_t* W2LO = sm + 17920;          // 8704
    uint32_t* HSHI = sm + 26624;          // 8704 (X-hi overlays first 4352)
    uint32_t* HSLO = sm + 35328;          // 8704 -> total 44032 u32 = 176128 B

    const int tid = threadIdx.x;
    const int w = tid >> 5, lane = tid & 31;
    const int gid = lane >> 2, tig = lane & 3;
    const int rowW = w & 7, colHalf = w >> 3;
    const int rA = rowW * 16 + gid, rB = rA + 8;

    // ---- prologue (once): W1, W2 -> SMEM fp16 hi/lo, half2-packed along c ----
    {
        const int o = tid >> 2, q = tid & 3;
#pragma unroll
        for (int i = 0; i < 4; ++i) {
            float4 v = *(const float4*)(w1 + o * CINCH + q * 16 + i * 4);
            int cp = q * 8 + 2 * i;
            uint32_t h, l;
            h2split(v.x, v.y, h, l); W1HI[o * W1S + cp] = h;     W1LO[o * W1S + cp] = l;
            h2split(v.z, v.w, h, l); W1HI[o * W1S + cp + 1] = h; W1LO[o * W1S + cp + 1] = l;
        }
#pragma unroll
        for (int i = 0; i < 8; ++i) {
            float4 v = *(const float4*)(w2 + o * COUTC + q * 32 + i * 4);
            int cp = q * 16 + 2 * i;
            uint32_t h, l;
            h2split(v.x, v.y, h, l); W2HI[o * W2S + cp] = h;     W2LO[o * W2S + cp] = l;
            h2split(v.z, v.w, h, l); W2HI[o * W2S + cp + 1] = h; W2LO[o * W2S + cp + 1] = l;
        }
    }

    // BN constants for rows rA, rB
    const float s1A = g1[rA] / sqrtf(v1[rA] + 1e-5f);
    const float c1A = b1[rA] - m1[rA] * s1A;
    const float s1B = g1[rB] / sqrtf(v1[rB] + 1e-5f);
    const float c1B = b1[rB] - m1[rB] * s1B;
    const float s2A = g2[rA] / sqrtf(v2[rA] + 1e-5f);
    const float c2A = b2[rA] - m2[rA] * s2A;
    const float s2B = g2[rB] / sqrtf(v2[rB] + 1e-5f);
    const float c2B = b2[rB] - m2[rB] * s2B;

    __half* HSHIh = (__half*)HSHI;   // half index = col*136 + o
    __half* HSLOh = (__half*)HSLO;

    for (int tile = blockIdx.x; tile < NTILES; tile += gridDim.x) {
        const int bIdx = tile >> 8;             // 256 tiles per batch
        const int np0  = (tile & 255) * 8;      // first point in batch

        // ---- gather + fp16 split: X[cp][col] (overlays HS) ----
        {
            const int col = tid & 127, q = tid >> 7;   // q: 16 channels each
            const int id = __ldg(&g_idx[tile * 128 + col]);
            const float4* src =
                (const float4*)(g_xt + ((size_t)bIdx * NPTS + id) * CINCH) + q * 4;
#pragma unroll
            for (int i = 0; i < 4; ++i) {
                float4 v = __ldg(&src[i]);
                int cp = q * 8 + 2 * i;
                uint32_t h, l;
                h2split(v.x, v.y, h, l);
                HSHI[cp * XS + col] = h; HSLO[cp * XS + col] = l;
                h2split(v.z, v.w, h, l);
                HSHI[(cp + 1) * XS + col] = h; HSLO[(cp + 1) * XS + col] = l;
            }
        }
        __syncthreads();

        float acc[8][4];
#pragma unroll
        for (int nt = 0; nt < 8; ++nt)
#pragma unroll
            for (int j = 0; j < 4; ++j) acc[nt][j] = 0.f;

        // ---- GEMM1: K=64 -> 4 k16-steps ----
#pragma unroll
        for (int s = 0; s < 4; ++s) {
            const int kp0 = s * 8;
            uint32_t A0h = W1HI[rA * W1S + kp0 + tig];
            uint32_t A1h = W1HI[rB * W1S + kp0 + tig];
            uint32_t A2h = W1HI[rA * W1S + kp0 + tig + 4];
            uint32_t A3h = W1HI[rB * W1S + kp0 + tig + 4];
            uint32_t A0l = W1LO[rA * W1S + kp0 + tig];
            uint32_t A1l = W1LO[rB * W1S + kp0 + tig];
            uint32_t A2l = W1LO[rA * W1S + kp0 + tig + 4];
            uint32_t A3l = W1LO[rB * W1S + kp0 + tig + 4];
#pragma unroll
            for (int nt = 0; nt < 8; ++nt) {
                const int col = colHalf * 64 + nt * 8 + gid;
                uint32_t B0h = HSHI[(kp0 + tig) * XS + col];
                uint32_t B1h = HSHI[(kp0 + tig + 4) * XS + col];
                uint32_t B0l = HSLO[(kp0 + tig) * XS + col];
                uint32_t B1l = HSLO[(kp0 + tig + 4) * XS + col];
                MMA_F16(acc[nt], A0h, A1h, A2h, A3h, B0h, B1h);
                MMA_F16(acc[nt], A0h, A1h, A2h, A3h, B0l, B1l);
                MMA_F16(acc[nt], A0l, A1l, A2l, A3l, B0h, B1h);
            }
        }
        __syncthreads();   // X fully consumed; HS region may now be overwritten

        // ---- epilogue 1: BN+ReLU -> HS (fp16 hi/lo, col-major) ----
#pragma unroll
        for (int nt = 0; nt < 8; ++nt) {
            const int colp = colHalf * 64 + nt * 8 + 2 * tig;
            float h0 = fmaxf(fmaf(acc[nt][0], s1A, c1A), 0.f);
            float h1 = fmaxf(fmaf(acc[nt][1], s1A, c1A), 0.f);
            float h2 = fmaxf(fmaf(acc[nt][2], s1B, c1B), 0.f);
            float h3 = fmaxf(fmaf(acc[nt][3], s1B, c1B), 0.f);
            __half hh, hl;
            hsplit(h0, hh, hl); HSHIh[colp * 136 + rA] = hh;       HSLOh[colp * 136 + rA] = hl;
            hsplit(h1, hh, hl); HSHIh[(colp + 1) * 136 + rA] = hh; HSLOh[(colp + 1) * 136 + rA] = hl;
            hsplit(h2, hh, hl); HSHIh[colp * 136 + rB] = hh;       HSLOh[colp * 136 + rB] = hl;
            hsplit(h3, hh, hl); HSHIh[(colp + 1) * 136 + rB] = hh; HSLOh[(colp + 1) * 136 + rB] = hl;
        }
        __syncthreads();

#pragma unroll
        for (int nt = 0; nt < 8; ++nt)
#pragma unroll
            for (int j = 0; j < 4; ++j) acc[nt][j] = 0.f;

        // ---- GEMM2: K=128 -> 8 k16-steps ----
#pragma unroll
        for (int s = 0; s < 8; ++s) {
            const int kp0 = s * 8;
            uint32_t A0h = W2HI[rA * W2S + kp0 + tig];
            uint32_t A1h = W2HI[rB * W2S + kp0 + tig];
            uint32_t A2h = W2HI[rA * W2S + kp0 + tig + 4];
            uint32_t A3h = W2HI[rB * W2S + kp0 + tig + 4];
            uint32_t A0l = W2LO[rA * W2S + kp0 + tig];
            uint32_t A1l = W2LO[rB * W2S + kp0 + tig];
            uint32_t A2l = W2LO[rA * W2S + kp0 + tig + 4];
            uint32_t A3l = W2LO[rB * W2S + kp0 + tig + 4];
#pragma unroll
            for (int nt = 0; nt < 8; ++nt) {
                const int col = colHalf * 64 + nt * 8 + gid;
                uint32_t B0h = HSHI[col * HSS + kp0 + tig];
                uint32_t B1h = HSHI[col * HSS + kp0 + tig + 4];
                uint32_t B0l = HSLO[col * HSS + kp0 + tig];
                uint32_t B1l = HSLO[col * HSS + kp0 + tig + 4];
                MMA_F16(acc[nt], A0h, A1h, A2h, A3h, B0h, B1h);
                MMA_F16(acc[nt], A0h, A1h, A2h, A3h, B0l, B1l);
                MMA_F16(acc[nt], A0l, A1l, A2l, A3l, B0h, B1h);
            }
        }

        // ---- epilogue 2: BN+ReLU, write knn_mlp_x + y ----
        {
            float* out2 = dout + OUT2_OFF;
            float pmA[4], pmB[4];
#pragma unroll
            for (int pp = 0; pp < 4; ++pp) { pmA[pp] = 0.f; pmB[pp] = 0.f; }
#pragma unroll
            for (int nt = 0; nt < 8; ++nt) {
                float v0 = fmaxf(fmaf(acc[nt][0], s2A, c2A), 0.f);
                float v1 = fmaxf(fmaf(acc[nt][1], s2A, c2A), 0.f);
                float v2_ = fmaxf(fmaf(acc[nt][2], s2B, c2B), 0.f);
                float v3 = fmaxf(fmaf(acc[nt][3], s2B, c2B), 0.f);
                const int pp = nt >> 1;
                const int kk = (nt & 1) * 8 + 2 * tig;
                pmA[pp] = fmaxf(pmA[pp], fmaxf(v0, v1));
                pmB[pp] = fmaxf(pmB[pp], fmaxf(v2_, v3));
                const int n = np0 + colHalf * 4 + pp;
                float* pA = out2 + (((size_t)(bIdx * COUTC + rA)) * NPTS + n) * KNNK + kk;
                float* pB = out2 + (((size_t)(bIdx * COUTC + rB)) * NPTS + n) * KNNK + kk;
                *(float2*)pA = make_float2(v0, v1);
                *(float2*)pB = make_float2(v2_, v3);
            }
#pragma unroll
            for (int pp = 0; pp < 4; ++pp) {
                float mA = pmA[pp], mB = pmB[pp];
                mA = fmaxf(mA, __shfl_xor_sync(0xffffffffu, mA, 1));
                mA = fmaxf(mA, __shfl_xor_sync(0xffffffffu, mA, 2));
                mB = fmaxf(mB, __shfl_xor_sync(0xffffffffu, mB, 1));
                mB = fmaxf(mB, __shfl_xor_sync(0xffffffffu, mB, 2));
                if (tig == 0) {
                    const int n = np0 + colHalf * 4 + pp;
                    dout[(size_t)(bIdx * COUTC + rA) * NPTS + n] = mA;
                    dout[(size_t)(bIdx * COUTC + rB) * NPTS + n] = mB;
                }
            }
        }
        __syncthreads();   // protect HS before next tile's gather overwrites it
    }
}

extern "C" void kernel_launch(void* const* d_in, const int* in_sizes, int n_in,
                              void* d_out, int out_size) {
    const float* x      = (const float*)d_in[0];
    const float* coords = (const float*)d_in[1];
    const float* w1     = (const float*)d_in[2];
    const float* g1     = (const float*)d_in[3];
    const float* b1     = (const float*)d_in[4];
    const float* m1     = (const float*)d_in[5];
    const float* v1     = (const float*)d_in[6];
    const float* w2     = (const float*)d_in[7];
    const float* g2     = (const float*)d_in[8];
    const float* b2     = (const float*)d_in[9];
    const float* m2     = (const float*)d_in[10];
    const float* v2     = (const float*)d_in[11];
    float* out = (float*)d_out;

    // knn first (independent of transpose) so ncu's capture window lands on it
    knn_kernel<<<BATCH * NPTS, 256>>>(coords, out);
    transpose_kernel<<<dim3(NPTS / 64, BATCH), 256>>>(x);

    const int smem_bytes = 44032 * 4;   // 176,128 B
    cudaFuncSetAttribute(mlp_mma_kernel, cudaFuncAttributeMaxDynamicSharedMemorySize, smem_bytes);
    mlp_mma_kernel<<<152, 512, smem_bytes>>>(
        w1, w2, g1, b1, m1, v1, g2, b2, m2, v2, out);
}

// round 16
// speedup vs baseline: 1.2981x; 1.2981x over previous
#include <cuda_runtime.h>
#include <cuda_fp16.h>
#include <cstdint>

#define NPTS  2048
#define BATCH 8
#define CINCH 64
#define COUTC 128
#define KNNK  16
#define NTILES 2048   // 8 points per tile

// d_out partitioning (float elements)
constexpr size_t OUT2_OFF = (size_t)BATCH * COUTC * NPTS;                     // 2,097,152
constexpr size_t LC_OFF   = OUT2_OFF + (size_t)BATCH * COUTC * NPTS * KNNK;   // 35,651,584

__device__ int   g_idx[BATCH * NPTS * KNNK];
__device__ float g_xt[BATCH * NPTS * CINCH];   // x transposed to [b][n][c]

__device__ __forceinline__ unsigned long long umin64(unsigned long long a,
                                                     unsigned long long b) {
    return a < b ? a : b;
}

__device__ __forceinline__ uint32_t packh2(__half a, __half b) {
    return (uint32_t)__half_as_ushort(a) | ((uint32_t)__half_as_ushort(b) << 16);
}
// fp16 hi/lo split of two floats -> packed hi pair, lo pair
__device__ __forceinline__ void h2split(float a, float b, uint32_t& hi, uint32_t& lo) {
    __half ah = __float2half_rn(a), bh = __float2half_rn(b);
    __half al = __float2half_rn(a - __half2float(ah));
    __half bl = __float2half_rn(b - __half2float(bh));
    hi = packh2(ah, bh);
    lo = packh2(al, bl);
}
__device__ __forceinline__ void hsplit(float a, __half& h, __half& l) {
    h = __float2half_rn(a);
    l = __float2half_rn(a - __half2float(h));
}

#define MMA_F16(c, a0, a1, a2, a3, b0, b1)                                       \
    asm volatile(                                                                \
        "mma.sync.aligned.m16n8k16.row.col.f32.f16.f16.f32 "                     \
        "{%0,%1,%2,%3}, {%4,%5,%6,%7}, {%8,%9}, {%0,%1,%2,%3};"                  \
        : "+f"((c)[0]), "+f"((c)[1]), "+f"((c)[2]), "+f"((c)[3])                 \
        : "r"(a0), "r"(a1), "r"(a2), "r"(a3), "r"(b0), "r"(b1))

// ---------- kernel 0: transpose x[b][c][n] -> g_xt[b][n][c] ----------
__global__ void __launch_bounds__(256) transpose_kernel(const float* __restrict__ x) {
    __shared__ float t[64][65];
    const int b = blockIdx.y, n0 = blockIdx.x * 64;
    const int tid = threadIdx.x;
    const int nn = tid & 63, cq = tid >> 6;
#pragma unroll
    for (int i = 0; i < 16; ++i) {
        int c = i * 4 + cq;
        t[c][nn] = x[((size_t)b * CINCH + c) * NPTS + n0 + nn];
    }
    __syncthreads();
    const int nr = tid >> 2, q = tid & 3;
    float4* dst = (float4*)(g_xt + ((size_t)b * NPTS + n0 + nr) * CINCH);
#pragma unroll
    for (int i = 0; i < 4; ++i) {
        int c4 = i * 4 + q;
        dst[c4] = make_float4(t[c4 * 4 + 0][nr], t[c4 * 4 + 1][nr],
                              t[c4 * 4 + 2][nr], t[c4 * 4 + 3][nr]);
    }
}

// ---------- kernel 1: KNN (top-16 ascending d2, tie -> smaller index) + local coords ----
// 128 threads x 16 keys. Round = shfl allreduce (4 warps) -> ONE bar -> merge-4
// (13 instrs) by all threads -> owner invalidates + recomputes. Winners in registers.
__global__ void __launch_bounds__(128, 8) knn_kernel(const float* __restrict__ coords,
                                                     float* __restrict__ dout) {
    const int bn = blockIdx.x;
    const int b = bn >> 11, n = bn & (NPTS - 1);
    const int tid = threadIdx.x;               // 128 threads
    const int w = tid >> 5, lane = tid & 31;
    const float* cb = coords + (size_t)b * 3 * NPTS;
    const float qx = cb[n], qy = cb[NPTS + n], qz = cb[2 * NPTS + n];
    const float sqn = __fadd_rn(__fadd_rn(__fmul_rn(qx, qx), __fmul_rn(qy, qy)),
                                __fmul_rn(qz, qz));

    unsigned long long keys[16];
#pragma unroll
    for (int i = 0; i < 16; ++i) {
        int m = tid + (i << 7);
        float mx = cb[m], my = cb[NPTS + m], mz = cb[2 * NPTS + m];
        float sqm = __fadd_rn(__fadd_rn(__fmul_rn(mx, mx), __fmul_rn(my, my)),
                              __fmul_rn(mz, mz));
        float dot = fmaf(qz, mz, fmaf(qy, my, __fmul_rn(qx, mx)));
        float t  = __fadd_rn(sqn, sqm);
        float d2 = __fsub_rn(t, __fmul_rn(2.0f, dot));
        unsigned u = __float_as_uint(d2);
        u = (u & 0x80000000u) ? ~u : (u | 0x80000000u);   // sortable float bits
        keys[i] = ((unsigned long long)u << 32) | (unsigned)m;
    }

    unsigned long long tmin = keys[0];
#pragma unroll
    for (int i = 1; i < 16; ++i) tmin = umin64(tmin, keys[i]);

    __shared__ unsigned long long wmin[2][4];
    unsigned long long mykey = 0;
    const int myr = tid & 15;

#pragma unroll 1
    for (int r = 0; r < KNNK; ++r) {
        unsigned long long v = tmin;
#pragma unroll
        for (int off = 16; off; off >>= 1)
            v = umin64(v, __shfl_xor_sync(0xffffffffu, v, off));
        if (lane == 0) wmin[r & 1][w] = v;
        __syncthreads();
        const unsigned long long* wm = wmin[r & 1];
        unsigned long long bb = umin64(umin64(wm[0], wm[1]), umin64(wm[2], wm[3]));
        if (myr == r) mykey = bb;
        if (tmin == bb) {                     // exactly one owner thread per block
#pragma unroll
            for (int i = 0; i < 16; ++i)
                keys[i] = (keys[i] == bb) ? ~0ull : keys[i];
            tmin = keys[0];
#pragma unroll
            for (int i = 1; i < 16; ++i) tmin = umin64(tmin, keys[i]);
        }
    }

    if (tid < KNNK) g_idx[bn * KNNK + tid] = (int)(mykey & 0xffffffffull);
    if (tid < 3 * KNNK) {
        int c = tid >> 4, k = tid & 15;  // k == myr
        int id = (int)(mykey & 0xffffffffull);
        float center = cb[c * NPTS + n];
        float nb = cb[c * NPTS + id];
        dout[LC_OFF + (((size_t)(b * 3 + c) * NPTS) + n) * KNNK + k] = __fsub_rn(center, nb);
    }
}

// ---------- kernel 2: persistent mma.sync 3xFP16-split MLP ----------
// 152 CTAs x 512 thr (16 warps). Tile = 8 points = 128 cols.
// Warp w: rows 16*(w&7)..+15, cols 64*(w>>3)..+63.
#define W1S 36
#define W2S 68
#define HSS 68
#define XS  136
__global__ void __launch_bounds__(512, 1) mlp_mma_kernel(
    const float* __restrict__ w1, const float* __restrict__ w2,
    const float* __restrict__ g1, const float* __restrict__ b1,
    const float* __restrict__ m1, const float* __restrict__ v1,
    const float* __restrict__ g2, const float* __restrict__ b2,
    const float* __restrict__ m2, const float* __restrict__ v2,
    float* __restrict__ dout) {
    extern __shared__ uint32_t sm[];
    uint32_t* W1HI = sm;                  // 4608
    uint32_t* W1LO = sm + 4608;           // 4608
    uint32_t* W2HI = sm + 9216;           // 8704
    uint32_t* W2LO = sm + 17920;          // 8704
    uint32_t* HSHI = sm + 26624;          // 8704 (X-hi overlays first 4352)
    uint32_t* HSLO = sm + 35328;          // 8704 -> total 44032 u32 = 176128 B

    const int tid = threadIdx.x;
    const int w = tid >> 5, lane = tid & 31;
    const int gid = lane >> 2, tig = lane & 3;
    const int rowW = w & 7, colHalf = w >> 3;
    const int rA = rowW * 16 + gid, rB = rA + 8;

    // ---- prologue (once): W1, W2 -> SMEM fp16 hi/lo, half2-packed along c ----
    {
        const int o = tid >> 2, q = tid & 3;
#pragma unroll
        for (int i = 0; i < 4; ++i) {
            float4 v = *(const float4*)(w1 + o * CINCH + q * 16 + i * 4);
            int cp = q * 8 + 2 * i;
            uint32_t h, l;
            h2split(v.x, v.y, h, l); W1HI[o * W1S + cp] = h;     W1LO[o * W1S + cp] = l;
            h2split(v.z, v.w, h, l); W1HI[o * W1S + cp + 1] = h; W1LO[o * W1S + cp + 1] = l;
        }
#pragma unroll
        for (int i = 0; i < 8; ++i) {
            float4 v = *(const float4*)(w2 + o * COUTC + q * 32 + i * 4);
            int cp = q * 16 + 2 * i;
            uint32_t h, l;
            h2split(v.x, v.y, h, l); W2HI[o * W2S + cp] = h;     W2LO[o * W2S + cp] = l;
            h2split(v.z, v.w, h, l); W2HI[o * W2S + cp + 1] = h; W2LO[o * W2S + cp + 1] = l;
        }
    }

    // BN constants for rows rA, rB
    const float s1A = g1[rA] / sqrtf(v1[rA] + 1e-5f);
    const float c1A = b1[rA] - m1[rA] * s1A;
    const float s1B = g1[rB] / sqrtf(v1[rB] + 1e-5f);
    const float c1B = b1[rB] - m1[rB] * s1B;
    const float s2A = g2[rA] / sqrtf(v2[rA] + 1e-5f);
    const float c2A = b2[rA] - m2[rA] * s2A;
    const float s2B = g2[rB] / sqrtf(v2[rB] + 1e-5f);
    const float c2B = b2[rB] - m2[rB] * s2B;

    __half* HSHIh = (__half*)HSHI;   // half index = col*136 + o
    __half* HSLOh = (__half*)HSLO;

    for (int tile = blockIdx.x; tile < NTILES; tile += gridDim.x) {
        const int bIdx = tile >> 8;             // 256 tiles per batch
        const int np0  = (tile & 255) * 8;      // first point in batch

        // ---- gather + fp16 split: X[cp][col] (overlays HS) ----
        {
            const int col = tid & 127, q = tid >> 7;   // q: 16 channels each
            const int id = __ldg(&g_idx[tile * 128 + col]);
            const float4* src =
                (const float4*)(g_xt + ((size_t)bIdx * NPTS + id) * CINCH) + q * 4;
#pragma unroll
            for (int i = 0; i < 4; ++i) {
                float4 v = __ldg(&src[i]);
                int cp = q * 8 + 2 * i;
                uint32_t h, l;
                h2split(v.x, v.y, h, l);
                HSHI[cp * XS + col] = h; HSLO[cp * XS + col] = l;
                h2split(v.z, v.w, h, l);
                HSHI[(cp + 1) * XS + col] = h; HSLO[(cp + 1) * XS + col] = l;
            }
        }
        __syncthreads();

        float acc[8][4];
#pragma unroll
        for (int nt = 0; nt < 8; ++nt)
#pragma unroll
            for (int j = 0; j < 4; ++j) acc[nt][j] = 0.f;

        // ---- GEMM1: K=64 -> 4 k16-steps ----
#pragma unroll
        for (int s = 0; s < 4; ++s) {
            const int kp0 = s * 8;
            uint32_t A0h = W1HI[rA * W1S + kp0 + tig];
            uint32_t A1h = W1HI[rB * W1S + kp0 + tig];
            uint32_t A2h = W1HI[rA * W1S + kp0 + tig + 4];
            uint32_t A3h = W1HI[rB * W1S + kp0 + tig + 4];
            uint32_t A0l = W1LO[rA * W1S + kp0 + tig];
            uint32_t A1l = W1LO[rB * W1S + kp0 + tig];
            uint32_t A2l = W1LO[rA * W1S + kp0 + tig + 4];
            uint32_t A3l = W1LO[rB * W1S + kp0 + tig + 4];
#pragma unroll
            for (int nt = 0; nt < 8; ++nt) {
                const int col = colHalf * 64 + nt * 8 + gid;
                uint32_t B0h = HSHI[(kp0 + tig) * XS + col];
                uint32_t B1h = HSHI[(kp0 + tig + 4) * XS + col];
                uint32_t B0l = HSLO[(kp0 + tig) * XS + col];
                uint32_t B1l = HSLO[(kp0 + tig + 4) * XS + col];
                MMA_F16(acc[nt], A0h, A1h, A2h, A3h, B0h, B1h);
                MMA_F16(acc[nt], A0h, A1h, A2h, A3h, B0l, B1l);
                MMA_F16(acc[nt], A0l, A1l, A2l, A3l, B0h, B1h);
            }
        }
        __syncthreads();   // X fully consumed; HS region may now be overwritten

        // ---- epilogue 1: BN+ReLU -> HS (fp16 hi/lo, col-major) ----
#pragma unroll
        for (int nt = 0; nt < 8; ++nt) {
            const int colp = colHalf * 64 + nt * 8 + 2 * tig;
            float h0 = fmaxf(fmaf(acc[nt][0], s1A, c1A), 0.f);
            float h1 = fmaxf(fmaf(acc[nt][1], s1A, c1A), 0.f);
            float h2 = fmaxf(fmaf(acc[nt][2], s1B, c1B), 0.f);
            float h3 = fmaxf(fmaf(acc[nt][3], s1B, c1B), 0.f);
            __half hh, hl;
            hsplit(h0, hh, hl); HSHIh[colp * 136 + rA] = hh;       HSLOh[colp * 136 + rA] = hl;
            hsplit(h1, hh, hl); HSHIh[(colp + 1) * 136 + rA] = hh; HSLOh[(colp + 1) * 136 + rA] = hl;
            hsplit(h2, hh, hl); HSHIh[colp * 136 + rB] = hh;       HSLOh[colp * 136 + rB] = hl;
            hsplit(h3, hh, hl); HSHIh[(colp + 1) * 136 + rB] = hh; HSLOh[(colp + 1) * 136 + rB] = hl;
        }
        __syncthreads();

#pragma unroll
        for (int nt = 0; nt < 8; ++nt)
#pragma unroll
            for (int j = 0; j < 4; ++j) acc[nt][j] = 0.f;

        // ---- GEMM2: K=128 -> 8 k16-steps ----
#pragma unroll
        for (int s = 0; s < 8; ++s) {
            const int kp0 = s * 8;
            uint32_t A0h = W2HI[rA * W2S + kp0 + tig];
            uint32_t A1h = W2HI[rB * W2S + kp0 + tig];
            uint32_t A2h = W2HI[rA * W2S + kp0 + tig + 4];
            uint32_t A3h = W2HI[rB * W2S + kp0 + tig + 4];
            uint32_t A0l = W2LO[rA * W2S + kp0 + tig];
            uint32_t A1l = W2LO[rB * W2S + kp0 + tig];
            uint32_t A2l = W2LO[rA * W2S + kp0 + tig + 4];
            uint32_t A3l = W2LO[rB * W2S + kp0 + tig + 4];
#pragma unroll
            for (int nt = 0; nt < 8; ++nt) {
                const int col = colHalf * 64 + nt * 8 + gid;
                uint32_t B0h = HSHI[col * HSS + kp0 + tig];
                uint32_t B1h = HSHI[col * HSS + kp0 + tig + 4];
                uint32_t B0l = HSLO[col * HSS + kp0 + tig];
                uint32_t B1l = HSLO[col * HSS + kp0 + tig + 4];
                MMA_F16(acc[nt], A0h, A1h, A2h, A3h, B0h, B1h);
                MMA_F16(acc[nt], A0h, A1h, A2h, A3h, B0l, B1l);
                MMA_F16(acc[nt], A0l, A1l, A2l, A3l, B0h, B1h);
            }
        }

        // ---- epilogue 2: BN+ReLU, write knn_mlp_x + y ----
        {
            float* out2 = dout + OUT2_OFF;
            float pmA[4], pmB[4];
#pragma unroll
            for (int pp = 0; pp < 4; ++pp) { pmA[pp] = 0.f; pmB[pp] = 0.f; }
#pragma unroll
            for (int nt = 0; nt < 8; ++nt) {
                float v0 = fmaxf(fmaf(acc[nt][0], s2A, c2A), 0.f);
                float v1 = fmaxf(fmaf(acc[nt][1], s2A, c2A), 0.f);
                float v2_ = fmaxf(fmaf(acc[nt][2], s2B, c2B), 0.f);
                float v3 = fmaxf(fmaf(acc[nt][3], s2B, c2B), 0.f);
                const int pp = nt >> 1;
                const int kk = (nt & 1) * 8 + 2 * tig;
                pmA[pp] = fmaxf(pmA[pp], fmaxf(v0, v1));
                pmB[pp] = fmaxf(pmB[pp], fmaxf(v2_, v3));
                const int n = np0 + colHalf * 4 + pp;
                float* pA = out2 + (((size_t)(bIdx * COUTC + rA)) * NPTS + n) * KNNK + kk;
                float* pB = out2 + (((size_t)(bIdx * COUTC + rB)) * NPTS + n) * KNNK + kk;
                *(float2*)pA = make_float2(v0, v1);
                *(float2*)pB = make_float2(v2_, v3);
            }
#pragma unroll
            for (int pp = 0; pp < 4; ++pp) {
                float mA = pmA[pp], mB = pmB[pp];
                mA = fmaxf(mA, __shfl_xor_sync(0xffffffffu, mA, 1));
                mA = fmaxf(mA, __shfl_xor_sync(0xffffffffu, mA, 2));
                mB = fmaxf(mB, __shfl_xor_sync(0xffffffffu, mB, 1));
                mB = fmaxf(mB, __shfl_xor_sync(0xffffffffu, mB, 2));
                if (tig == 0) {
                    const int n = np0 + colHalf * 4 + pp;
                    dout[(size_t)(bIdx * COUTC + rA) * NPTS + n] = mA;
                    dout[(size_t)(bIdx * COUTC + rB) * NPTS + n] = mB;
                }
            }
        }
        __syncthreads();   // protect HS before next tile's gather overwrites it
    }
}

extern "C" void kernel_launch(void* const* d_in, const int* in_sizes, int n_in,
                              void* d_out, int out_size) {
    const float* x      = (const float*)d_in[0];
    const float* coords = (const float*)d_in[1];
    const float* w1     = (const float*)d_in[2];
    const float* g1     = (const float*)d_in[3];
    const float* b1     = (const float*)d_in[4];
    const float* m1     = (const float*)d_in[5];
    const float* v1     = (const float*)d_in[6];
    const float* w2     = (const float*)d_in[7];
    const float* g2     = (const float*)d_in[8];
    const float* b2     = (const float*)d_in[9];
    const float* m2     = (const float*)d_in[10];
    const float* v2     = (const float*)d_in[11];
    float* out = (float*)d_out;

    // knn first so ncu's capture window lands on it
    knn_kernel<<<BATCH * NPTS, 128>>>(coords, out);
    transpose_kernel<<<dim3(NPTS / 64, BATCH), 256>>>(x);

    const int smem_bytes = 44032 * 4;   // 176,128 B
    cudaFuncSetAttribute(mlp_mma_kernel, cudaFuncAttributeMaxDynamicSharedMemorySize, smem_bytes);
    mlp_mma_kernel<<<152, 512, smem_bytes>>>(
        w1, w2, g1, b1, m1, v1, g2, b2, m2, v2, out);
}